// round 1
// baseline (speedup 1.0000x reference)
#include <cuda_runtime.h>
#include <math.h>

#define DM   1024
#define NTOK 4096
#define SEQ  2048
#define NH   16

// Scratch (allocation-free rule: __device__ globals)
__device__ float g_Xn[NTOK * DM];
__device__ float g_Q [NTOK * DM];
__device__ float g_K [NTOK * DM];
__device__ float g_V [NTOK * DM];
__device__ float g_M [NTOK * DM];

// ---------------------------------------------------------------------------
// LayerNorm: one block per token row (1024 floats), 256 threads, float4 IO.
// ---------------------------------------------------------------------------
__global__ void ln_kernel(const float* __restrict__ X, const float* __restrict__ w,
                          const float* __restrict__ b, float* __restrict__ out) {
    int row = blockIdx.x;
    int t = threadIdx.x;
    const float4* xr = reinterpret_cast<const float4*>(X + (size_t)row * DM);
    float4 v = xr[t];
    float s  = v.x + v.y + v.z + v.w;
    float s2 = v.x * v.x + v.y * v.y + v.z * v.z + v.w * v.w;
    __shared__ float rs[8], rs2[8];
#pragma unroll
    for (int o = 16; o > 0; o >>= 1) {
        s  += __shfl_xor_sync(0xffffffffu, s,  o);
        s2 += __shfl_xor_sync(0xffffffffu, s2, o);
    }
    if ((t & 31) == 0) { rs[t >> 5] = s; rs2[t >> 5] = s2; }
    __syncthreads();
    float S = 0.f, S2 = 0.f;
#pragma unroll
    for (int i = 0; i < 8; i++) { S += rs[i]; S2 += rs2[i]; }
    float mu  = S * (1.0f / DM);
    float var = S2 * (1.0f / DM) - mu * mu;
    float inv = rsqrtf(var + 1e-4f);
    float4 wv = reinterpret_cast<const float4*>(w)[t];
    float4 bv = reinterpret_cast<const float4*>(b)[t];
    float4 o;
    o.x = (v.x - mu) * inv * wv.x + bv.x;
    o.y = (v.y - mu) * inv * wv.y + bv.y;
    o.z = (v.z - mu) * inv * wv.z + bv.z;
    o.w = (v.w - mu) * inv * wv.w + bv.w;
    reinterpret_cast<float4*>(out + (size_t)row * DM)[t] = o;
}

// ---------------------------------------------------------------------------
// GEMM: C[4096,1024] = A[4096,1024] @ W[1024,1024] + bias.
// 64x64 tile, BK=16, 256 threads, 4x4 register block.
// ---------------------------------------------------------------------------
__global__ void gemm_bias(const float* __restrict__ A, const float* __restrict__ W,
                          const float* __restrict__ bias, float* __restrict__ C) {
    const int Kd = DM, N = DM;
    __shared__ float As[16][65];   // transposed A tile [k][m], padded
    __shared__ float Bs[16][64];   // W tile [k][n]
    int tid = threadIdx.x;
    int tx = tid & 15, ty = tid >> 4;
    int m0 = blockIdx.y << 6, n0 = blockIdx.x << 6;
    float acc[4][4] = {};

    int am  = tid >> 2;           // 0..63
    int ak  = (tid & 3) << 2;     // 0,4,8,12
    int bkr = tid >> 4;           // 0..15
    int bn  = (tid & 15) << 2;    // 0..60
    const float* Ap = A + (size_t)(m0 + am) * Kd + ak;
    const float* Wp = W + (size_t)bkr * N + n0 + bn;

    for (int k0 = 0; k0 < Kd; k0 += 16) {
        float4 a4 = *reinterpret_cast<const float4*>(Ap + k0);
        As[ak + 0][am] = a4.x; As[ak + 1][am] = a4.y;
        As[ak + 2][am] = a4.z; As[ak + 3][am] = a4.w;
        float4 b4 = *reinterpret_cast<const float4*>(Wp + (size_t)k0 * N);
        *reinterpret_cast<float4*>(&Bs[bkr][bn]) = b4;
        __syncthreads();
#pragma unroll
        for (int k = 0; k < 16; k++) {
            float ra[4];
#pragma unroll
            for (int i = 0; i < 4; i++) ra[i] = As[k][(ty << 2) + i];
            float4 b4c = *reinterpret_cast<const float4*>(&Bs[k][tx << 2]);
            float rb[4] = {b4c.x, b4c.y, b4c.z, b4c.w};
#pragma unroll
            for (int i = 0; i < 4; i++)
#pragma unroll
                for (int j = 0; j < 4; j++)
                    acc[i][j] += ra[i] * rb[j];
        }
        __syncthreads();
    }
    float4 bb = *reinterpret_cast<const float4*>(bias + n0 + (tx << 2));
#pragma unroll
    for (int i = 0; i < 4; i++) {
        int m = m0 + (ty << 2) + i;
        float4 o;
        o.x = acc[i][0] + bb.x; o.y = acc[i][1] + bb.y;
        o.z = acc[i][2] + bb.z; o.w = acc[i][3] + bb.w;
        *reinterpret_cast<float4*>(C + (size_t)m * N + n0 + (tx << 2)) = o;
    }
}

// ---------------------------------------------------------------------------
// Flash-style causal attention. Grid: (qt=32, bh=32). Block: 256 threads.
// Q/K/V read directly from [4096,1024] projection buffers at col offset h*64.
// Dynamic smem: Qs,Ks,Vs,Ps each [64][65] floats = 66,560 B.
// Thread (tx,ty) owns rows r0..r0+3, cols c0..c0+3 (k-cols for S, Dh-cols for O).
// ---------------------------------------------------------------------------
__global__ void attn_kernel(const float* __restrict__ Q, const float* __restrict__ K,
                            const float* __restrict__ V, float* __restrict__ O) {
    extern __shared__ float sm[];
    float (*Qs)[65] = reinterpret_cast<float(*)[65]>(sm);
    float (*Ks)[65] = reinterpret_cast<float(*)[65]>(sm + 64 * 65);
    float (*Vs)[65] = reinterpret_cast<float(*)[65]>(sm + 2 * 64 * 65);
    float (*Ps)[65] = reinterpret_cast<float(*)[65]>(sm + 3 * 64 * 65);

    int qt = blockIdx.x;
    int bh = blockIdx.y;
    int b = bh >> 4, h = bh & 15;
    int cb = h << 6;
    int qbase = b * SEQ + (qt << 6);
    int tid = threadIdx.x;
    int tx = tid & 15, ty = tid >> 4;
    int r0 = ty << 2;
    int c0 = tx << 2;

    for (int idx = tid; idx < 64 * 64; idx += 256) {
        int rr = idx >> 6, d = idx & 63;
        Qs[rr][d] = Q[(size_t)(qbase + rr) * DM + cb + d] * 0.125f;  // 1/sqrt(64)
    }
    float m[4], l[4];
    float acc[4][4] = {};
#pragma unroll
    for (int i = 0; i < 4; i++) { m[i] = -INFINITY; l[i] = 0.f; }

    for (int kt = 0; kt <= qt; kt++) {
        int kbase = b * SEQ + (kt << 6);
        __syncthreads();   // previous iteration's Ps/Vs reads done
        for (int idx = tid; idx < 64 * 64; idx += 256) {
            int rr = idx >> 6, d = idx & 63;
            Ks[rr][d] = K[(size_t)(kbase + rr) * DM + cb + d];
            Vs[rr][d] = V[(size_t)(kbase + rr) * DM + cb + d];
        }
        __syncthreads();

        // S = Q K^T (64x64x64), 4x4 per thread
        float sc[4][4] = {};
#pragma unroll 8
        for (int d = 0; d < 64; d++) {
            float ra[4], rb[4];
#pragma unroll
            for (int i = 0; i < 4; i++) ra[i] = Qs[r0 + i][d];
#pragma unroll
            for (int j = 0; j < 4; j++) rb[j] = Ks[c0 + j][d];
#pragma unroll
            for (int i = 0; i < 4; i++)
#pragma unroll
                for (int j = 0; j < 4; j++)
                    sc[i][j] += ra[i] * rb[j];
        }
        if (kt == qt) {
#pragma unroll
            for (int i = 0; i < 4; i++)
#pragma unroll
                for (int j = 0; j < 4; j++)
                    if (c0 + j > r0 + i) sc[i][j] = -INFINITY;
        }

        // Online softmax: reduce across the 16 tx lanes (same warp half).
#pragma unroll
        for (int i = 0; i < 4; i++) {
            float tmax = fmaxf(fmaxf(sc[i][0], sc[i][1]), fmaxf(sc[i][2], sc[i][3]));
#pragma unroll
            for (int o = 8; o > 0; o >>= 1)
                tmax = fmaxf(tmax, __shfl_xor_sync(0xffffffffu, tmax, o));
            float mn = fmaxf(m[i], tmax);
            float scale = __expf(m[i] - mn);   // m=-inf on first tile -> 0
            float ps = 0.f;
#pragma unroll
            for (int j = 0; j < 4; j++) {
                float p = __expf(sc[i][j] - mn);  // masked -> exp(-inf)=0
                sc[i][j] = p;
                ps += p;
            }
#pragma unroll
            for (int o = 8; o > 0; o >>= 1)
                ps += __shfl_xor_sync(0xffffffffu, ps, o);
            l[i] = l[i] * scale + ps;
            m[i] = mn;
#pragma unroll
            for (int j = 0; j < 4; j++) acc[i][j] *= scale;
        }

        // stage P through smem so every thread sees all 64 k per row
#pragma unroll
        for (int i = 0; i < 4; i++)
#pragma unroll
            for (int j = 0; j < 4; j++)
                Ps[r0 + i][c0 + j] = sc[i][j];
        __syncthreads();

        // O += P @ V (64x64x64)
#pragma unroll 8
        for (int k = 0; k < 64; k++) {
            float ra[4], rb[4];
#pragma unroll
            for (int i = 0; i < 4; i++) ra[i] = Ps[r0 + i][k];
#pragma unroll
            for (int j = 0; j < 4; j++) rb[j] = Vs[k][c0 + j];
#pragma unroll
            for (int i = 0; i < 4; i++)
#pragma unroll
                for (int j = 0; j < 4; j++)
                    acc[i][j] += ra[i] * rb[j];
        }
    }

#pragma unroll
    for (int i = 0; i < 4; i++) {
        float inv = 1.0f / l[i];
        float4 o;
        o.x = acc[i][0] * inv; o.y = acc[i][1] * inv;
        o.z = acc[i][2] * inv; o.w = acc[i][3] * inv;
        *reinterpret_cast<float4*>(O + (size_t)(qbase + r0 + i) * DM + cb + c0) = o;
    }
}

// ---------------------------------------------------------------------------
extern "C" void kernel_launch(void* const* d_in, const int* in_sizes, int n_in,
                              void* d_out, int out_size) {
    const float* X   = (const float*)d_in[0];
    const float* lnw = (const float*)d_in[1];
    const float* lnb = (const float*)d_in[2];
    const float* Wq  = (const float*)d_in[3];
    const float* bq  = (const float*)d_in[4];
    const float* Wk  = (const float*)d_in[5];
    const float* bk  = (const float*)d_in[6];
    const float* Wv  = (const float*)d_in[7];
    const float* bv  = (const float*)d_in[8];
    const float* Wo  = (const float*)d_in[9];
    const float* bo  = (const float*)d_in[10];
    float* out = (float*)d_out;
    (void)in_sizes; (void)n_in; (void)out_size;

    float *Xn, *Qb, *Kb, *Vb, *Mb;
    cudaGetSymbolAddress((void**)&Xn, g_Xn);
    cudaGetSymbolAddress((void**)&Qb, g_Q);
    cudaGetSymbolAddress((void**)&Kb, g_K);
    cudaGetSymbolAddress((void**)&Vb, g_V);
    cudaGetSymbolAddress((void**)&Mb, g_M);

    const int ATTN_SMEM = 4 * 64 * 65 * (int)sizeof(float);  // 66,560 B
    cudaFuncSetAttribute(attn_kernel, cudaFuncAttributeMaxDynamicSharedMemorySize,
                         ATTN_SMEM);

    ln_kernel<<<NTOK, 256>>>(X, lnw, lnb, Xn);

    dim3 ggrid(DM / 64, NTOK / 64);   // (16, 64)
    gemm_bias<<<ggrid, 256>>>(Xn, Wq, bq, Qb);
    gemm_bias<<<ggrid, 256>>>(Xn, Wk, bk, Kb);
    gemm_bias<<<ggrid, 256>>>(Xn, Wv, bv, Vb);

    dim3 agrid(SEQ / 64, 2 * NH);     // (32, 32)
    attn_kernel<<<agrid, 256, ATTN_SMEM>>>(Qb, Kb, Vb, Mb);

    gemm_bias<<<ggrid, 256>>>(Mb, Wo, bo, out);
}

// round 3
// speedup vs baseline: 3.1997x; 3.1997x over previous
#include <cuda_runtime.h>
#include <math.h>
#include <stdint.h>

#define DM   1024
#define NTOK 4096
#define SEQ  2048
#define NH   16

// Scratch (allocation-free rule: __device__ globals)
__device__ float g_Xn[NTOK * DM];
__device__ float g_Q [NTOK * DM];
__device__ float g_K [NTOK * DM];
__device__ float g_V [NTOK * DM];
__device__ float g_M [NTOK * DM];
__device__ float g_Wt[DM * DM];      // tf32-rounded weight staging (reused)

// ---------------------------------------------------------------------------
// helpers
// ---------------------------------------------------------------------------
__device__ __forceinline__ uint32_t smem_u32(const void* p) {
    uint32_t a;
    asm("{ .reg .u64 t; cvta.to.shared.u64 t, %1; cvt.u32.u64 %0, t; }" : "=r"(a) : "l"(p));
    return a;
}
__device__ __forceinline__ uint32_t tf32u(float x) {
    uint32_t u; asm("cvt.rna.tf32.f32 %0, %1;" : "=r"(u) : "f"(x));
    return u;
}
__device__ __forceinline__ float tf32f(float x) { return __uint_as_float(tf32u(x)); }

__device__ __forceinline__ void mma_tf32(float* d, const uint32_t* a,
                                         uint32_t b0, uint32_t b1) {
    asm volatile(
        "mma.sync.aligned.m16n8k8.row.col.f32.tf32.tf32.f32 "
        "{%0,%1,%2,%3}, {%4,%5,%6,%7}, {%8,%9}, {%0,%1,%2,%3};"
        : "+f"(d[0]), "+f"(d[1]), "+f"(d[2]), "+f"(d[3])
        : "r"(a[0]), "r"(a[1]), "r"(a[2]), "r"(a[3]), "r"(b0), "r"(b1));
}

#define CP_ASYNC16(dst, src) \
    asm volatile("cp.async.cg.shared.global [%0], [%1], 16;" :: "r"(dst), "l"(src) : "memory")
#define CP_COMMIT() asm volatile("cp.async.commit_group;" ::: "memory")
#define CP_WAIT(n)  asm volatile("cp.async.wait_group %0;" :: "n"(n) : "memory")

// ---------------------------------------------------------------------------
// LayerNorm (tf32-rounded output: feeds tf32 MMAs)
// ---------------------------------------------------------------------------
__global__ void ln_kernel(const float* __restrict__ X, const float* __restrict__ w,
                          const float* __restrict__ b, float* __restrict__ out) {
    int row = blockIdx.x;
    int t = threadIdx.x;
    const float4* xr = reinterpret_cast<const float4*>(X + (size_t)row * DM);
    float4 v = xr[t];
    float s  = v.x + v.y + v.z + v.w;
    float s2 = v.x * v.x + v.y * v.y + v.z * v.z + v.w * v.w;
    __shared__ float rs[8], rs2[8];
#pragma unroll
    for (int o = 16; o > 0; o >>= 1) {
        s  += __shfl_xor_sync(0xffffffffu, s,  o);
        s2 += __shfl_xor_sync(0xffffffffu, s2, o);
    }
    if ((t & 31) == 0) { rs[t >> 5] = s; rs2[t >> 5] = s2; }
    __syncthreads();
    float S = 0.f, S2 = 0.f;
#pragma unroll
    for (int i = 0; i < 8; i++) { S += rs[i]; S2 += rs2[i]; }
    float mu  = S * (1.0f / DM);
    float var = S2 * (1.0f / DM) - mu * mu;
    float inv = rsqrtf(var + 1e-4f);
    float4 wv = reinterpret_cast<const float4*>(w)[t];
    float4 bv = reinterpret_cast<const float4*>(b)[t];
    float4 o;
    o.x = tf32f((v.x - mu) * inv * wv.x + bv.x);
    o.y = tf32f((v.y - mu) * inv * wv.y + bv.y);
    o.z = tf32f((v.z - mu) * inv * wv.z + bv.z);
    o.w = tf32f((v.w - mu) * inv * wv.w + bv.w);
    reinterpret_cast<float4*>(out + (size_t)row * DM)[t] = o;
}

// ---------------------------------------------------------------------------
// Elementwise tf32 round of a weight matrix (RNE beats HW truncation)
// ---------------------------------------------------------------------------
__global__ void round_tf32(const float* __restrict__ W, float* __restrict__ Wt) {
    int i = blockIdx.x * 256 + threadIdx.x;
    float4 v = reinterpret_cast<const float4*>(W)[i];
    float4 o = { tf32f(v.x), tf32f(v.y), tf32f(v.z), tf32f(v.w) };
    reinterpret_cast<float4*>(Wt)[i] = o;
}

// ---------------------------------------------------------------------------
// tf32 mma.sync GEMM: C[4096,1024] = A @ W + bias
// 128x128x32 tiles, 8 warps (2M x 4N), cp.async double buffer.
// ---------------------------------------------------------------------------
#define APAD 36
#define BPAD 136
#define A_ST (128 * APAD)               // floats per A stage (4608)
#define B_ST (32 * BPAD)                // floats per B stage (4352)
#define GEMM_SMEM ((2 * (A_ST + B_ST)) * 4)   // 71680 B

__global__ void __launch_bounds__(256)
gemm_mma(const float* __restrict__ A, const float* __restrict__ W,
         const float* __restrict__ bias, float* __restrict__ C) {
    extern __shared__ __align__(16) float sm[];
    float* Asm[2] = { sm, sm + A_ST };
    float* Bsm[2] = { sm + 2 * A_ST, sm + 2 * A_ST + B_ST };
    uint32_t aAddr[2] = { smem_u32(Asm[0]), smem_u32(Asm[1]) };
    uint32_t bAddr[2] = { smem_u32(Bsm[0]), smem_u32(Bsm[1]) };

    int tid = threadIdx.x, lane = tid & 31, wid = tid >> 5;
    int r = lane >> 2, cg = lane & 3;
    int wm = wid & 1, wn = wid >> 1;
    int m0 = blockIdx.y * 128, n0 = blockIdx.x * 128;

    float acc[4][4][4];
#pragma unroll
    for (int i = 0; i < 4; i++)
#pragma unroll
        for (int j = 0; j < 4; j++)
#pragma unroll
            for (int k = 0; k < 4; k++) acc[i][j][k] = 0.f;

    auto load_tile = [&](int t, int buf) {
        int k0 = t * 32;
#pragma unroll
        for (int i = 0; i < 4; i++) {          // A: 1024 float4
            int idx = i * 256 + tid;
            int row = idx >> 3, c4 = (idx & 7) << 2;
            uint32_t dst = aAddr[buf] + (uint32_t)(row * APAD + c4) * 4u;
            const float* src = A + (size_t)(m0 + row) * DM + k0 + c4;
            CP_ASYNC16(dst, src);
        }
#pragma unroll
        for (int i = 0; i < 4; i++) {          // B: 1024 float4
            int idx = i * 256 + tid;
            int row = idx >> 5, c4 = (idx & 31) << 2;
            uint32_t dst = bAddr[buf] + (uint32_t)(row * BPAD + c4) * 4u;
            const float* src = W + (size_t)(k0 + row) * DM + n0 + c4;
            CP_ASYNC16(dst, src);
        }
        CP_COMMIT();
    };

    load_tile(0, 0);
    const int NT = DM / 32;
    for (int t = 0; t < NT; t++) {
        int buf = t & 1;
        if (t + 1 < NT) { load_tile(t + 1, (t + 1) & 1); CP_WAIT(1); }
        else            { CP_WAIT(0); }
        __syncthreads();

        const uint32_t* As = reinterpret_cast<const uint32_t*>(Asm[buf]);
        const uint32_t* Bs = reinterpret_cast<const uint32_t*>(Bsm[buf]);
#pragma unroll
        for (int kk = 0; kk < 4; kk++) {
            int kb = kk * 8;
            uint32_t aF[4][4];
#pragma unroll
            for (int mt = 0; mt < 4; mt++) {
                int mr = wm * 64 + mt * 16 + r;
                aF[mt][0] = As[mr * APAD + kb + cg];
                aF[mt][1] = As[(mr + 8) * APAD + kb + cg];
                aF[mt][2] = As[mr * APAD + kb + cg + 4];
                aF[mt][3] = As[(mr + 8) * APAD + kb + cg + 4];
            }
            uint32_t bF[4][2];
#pragma unroll
            for (int nt = 0; nt < 4; nt++) {
                int nc = wn * 32 + nt * 8 + r;
                bF[nt][0] = Bs[(kb + cg) * BPAD + nc];
                bF[nt][1] = Bs[(kb + cg + 4) * BPAD + nc];
            }
#pragma unroll
            for (int mt = 0; mt < 4; mt++)
#pragma unroll
                for (int nt = 0; nt < 4; nt++)
                    mma_tf32(acc[mt][nt], aF[mt], bF[nt][0], bF[nt][1]);
        }
        __syncthreads();
    }

    // epilogue
    const float* bp = bias + n0 + wn * 32;
#pragma unroll
    for (int nt = 0; nt < 4; nt++) {
        float2 bb = *reinterpret_cast<const float2*>(bp + nt * 8 + 2 * cg);
#pragma unroll
        for (int mt = 0; mt < 4; mt++) {
            int row = m0 + wm * 64 + mt * 16 + r;
            float* c0 = C + (size_t)row * DM + n0 + wn * 32 + nt * 8 + 2 * cg;
            float* c1 = C + (size_t)(row + 8) * DM + n0 + wn * 32 + nt * 8 + 2 * cg;
            float2 v0 = { acc[mt][nt][0] + bb.x, acc[mt][nt][1] + bb.y };
            float2 v1 = { acc[mt][nt][2] + bb.x, acc[mt][nt][3] + bb.y };
            *reinterpret_cast<float2*>(c0) = v0;
            *reinterpret_cast<float2*>(c1) = v1;
        }
    }
}

// ---------------------------------------------------------------------------
// Flash attention with mma.sync tf32. 128 threads, q-tile 64, head 64.
// Warp w owns q rows [16w, 16w+16). Q fragments live in registers.
// ---------------------------------------------------------------------------
#define ATT_PAD 68
#define ATTN_SMEM (3 * 64 * ATT_PAD * 4)   // Ks, Vs, Ps = 52224 B

__global__ void __launch_bounds__(128)
attn_mma(const float* __restrict__ Q, const float* __restrict__ K,
         const float* __restrict__ V, float* __restrict__ O) {
    extern __shared__ __align__(16) float sm[];
    float* Ks = sm;
    float* Vs = sm + 64 * ATT_PAD;
    float* Ps = sm + 2 * 64 * ATT_PAD;
    const uint32_t* KsU = reinterpret_cast<const uint32_t*>(Ks);
    const uint32_t* VsU = reinterpret_cast<const uint32_t*>(Vs);
    const uint32_t* PsU = reinterpret_cast<const uint32_t*>(Ps);

    int tid = threadIdx.x, lane = tid & 31, wid = tid >> 5;
    int qt = blockIdx.x, bh = blockIdx.y;
    int b = bh >> 4, h = bh & 15, cb = h << 6;
    int qbase = b * SEQ + (qt << 6);
    int r = lane >> 2, cg = lane & 3;
    int qrow = (wid << 4) + r;            // local 0..63 (plus +8 in frags)

    // Q fragments (scaled, tf32-rounded) — one-time load
    uint32_t aQ[8][4];
    const float* Q0 = Q + (size_t)(qbase + qrow) * DM + cb;
    const float* Q1 = Q + (size_t)(qbase + qrow + 8) * DM + cb;
#pragma unroll
    for (int kk = 0; kk < 8; kk++) {
        aQ[kk][0] = tf32u(Q0[kk * 8 + cg] * 0.125f);
        aQ[kk][1] = tf32u(Q1[kk * 8 + cg] * 0.125f);
        aQ[kk][2] = tf32u(Q0[kk * 8 + cg + 4] * 0.125f);
        aQ[kk][3] = tf32u(Q1[kk * 8 + cg + 4] * 0.125f);
    }

    float m0 = -INFINITY, m1 = -INFINITY, l0 = 0.f, l1 = 0.f;
    float oc[8][4];
#pragma unroll
    for (int i = 0; i < 8; i++)
#pragma unroll
        for (int j = 0; j < 4; j++) oc[i][j] = 0.f;

    for (int kt = 0; kt <= qt; kt++) {
        const float* Kg = K + (size_t)(b * SEQ + (kt << 6)) * DM + cb;
        const float* Vg = V + (size_t)(b * SEQ + (kt << 6)) * DM + cb;
        __syncthreads();    // previous iteration's smem reads complete
#pragma unroll
        for (int i = 0; i < 8; i++) {
            int idx = i * 128 + tid;
            int row = idx >> 4, d4 = (idx & 15) << 2;
            float4 kv = *reinterpret_cast<const float4*>(Kg + (size_t)row * DM + d4);
            float4 vv = *reinterpret_cast<const float4*>(Vg + (size_t)row * DM + d4);
            float4 ko = { tf32f(kv.x), tf32f(kv.y), tf32f(kv.z), tf32f(kv.w) };
            float4 vo = { tf32f(vv.x), tf32f(vv.y), tf32f(vv.z), tf32f(vv.w) };
            *reinterpret_cast<float4*>(Ks + row * ATT_PAD + d4) = ko;
            *reinterpret_cast<float4*>(Vs + row * ATT_PAD + d4) = vo;
        }
        __syncthreads();

        // S = Q K^T
        float sc[8][4];
#pragma unroll
        for (int nt = 0; nt < 8; nt++) {
#pragma unroll
            for (int j = 0; j < 4; j++) sc[nt][j] = 0.f;
#pragma unroll
            for (int kk = 0; kk < 8; kk++) {
                uint32_t b0 = KsU[(nt * 8 + r) * ATT_PAD + kk * 8 + cg];
                uint32_t b1 = KsU[(nt * 8 + r) * ATT_PAD + kk * 8 + cg + 4];
                mma_tf32(sc[nt], aQ[kk], b0, b1);
            }
        }

        if (kt == qt) {
#pragma unroll
            for (int nt = 0; nt < 8; nt++) {
                int col = nt * 8 + 2 * cg;
                if (col > qrow)         sc[nt][0] = -INFINITY;
                if (col + 1 > qrow)     sc[nt][1] = -INFINITY;
                if (col > qrow + 8)     sc[nt][2] = -INFINITY;
                if (col + 1 > qrow + 8) sc[nt][3] = -INFINITY;
            }
        }

        // online softmax (rows qrow / qrow+8), quad reduction
        float mx0 = -INFINITY, mx1 = -INFINITY;
#pragma unroll
        for (int nt = 0; nt < 8; nt++) {
            mx0 = fmaxf(mx0, fmaxf(sc[nt][0], sc[nt][1]));
            mx1 = fmaxf(mx1, fmaxf(sc[nt][2], sc[nt][3]));
        }
        mx0 = fmaxf(mx0, __shfl_xor_sync(0xffffffffu, mx0, 1));
        mx0 = fmaxf(mx0, __shfl_xor_sync(0xffffffffu, mx0, 2));
        mx1 = fmaxf(mx1, __shfl_xor_sync(0xffffffffu, mx1, 1));
        mx1 = fmaxf(mx1, __shfl_xor_sync(0xffffffffu, mx1, 2));
        float mn0 = fmaxf(m0, mx0), mn1 = fmaxf(m1, mx1);
        float sc0 = __expf(m0 - mn0), sc1 = __expf(m1 - mn1);
        float s0 = 0.f, s1 = 0.f;
#pragma unroll
        for (int nt = 0; nt < 8; nt++) {
            sc[nt][0] = __expf(sc[nt][0] - mn0);
            sc[nt][1] = __expf(sc[nt][1] - mn0);
            sc[nt][2] = __expf(sc[nt][2] - mn1);
            sc[nt][3] = __expf(sc[nt][3] - mn1);
            s0 += sc[nt][0] + sc[nt][1];
            s1 += sc[nt][2] + sc[nt][3];
        }
        s0 += __shfl_xor_sync(0xffffffffu, s0, 1);
        s0 += __shfl_xor_sync(0xffffffffu, s0, 2);
        s1 += __shfl_xor_sync(0xffffffffu, s1, 1);
        s1 += __shfl_xor_sync(0xffffffffu, s1, 2);
        l0 = l0 * sc0 + s0; m0 = mn0;
        l1 = l1 * sc1 + s1; m1 = mn1;
#pragma unroll
        for (int dt = 0; dt < 8; dt++) {
            oc[dt][0] *= sc0; oc[dt][1] *= sc0;
            oc[dt][2] *= sc1; oc[dt][3] *= sc1;
        }

        // stage P (tf32-rounded)
#pragma unroll
        for (int nt = 0; nt < 8; nt++) {
            float2 p0 = { tf32f(sc[nt][0]), tf32f(sc[nt][1]) };
            float2 p1 = { tf32f(sc[nt][2]), tf32f(sc[nt][3]) };
            *reinterpret_cast<float2*>(Ps + qrow * ATT_PAD + nt * 8 + 2 * cg) = p0;
            *reinterpret_cast<float2*>(Ps + (qrow + 8) * ATT_PAD + nt * 8 + 2 * cg) = p1;
        }
        __syncthreads();

        // O += P @ V
#pragma unroll
        for (int kk = 0; kk < 8; kk++) {
            uint32_t aP[4];
            aP[0] = PsU[qrow * ATT_PAD + kk * 8 + cg];
            aP[1] = PsU[(qrow + 8) * ATT_PAD + kk * 8 + cg];
            aP[2] = PsU[qrow * ATT_PAD + kk * 8 + cg + 4];
            aP[3] = PsU[(qrow + 8) * ATT_PAD + kk * 8 + cg + 4];
#pragma unroll
            for (int dt = 0; dt < 8; dt++) {
                uint32_t b0 = VsU[(kk * 8 + cg) * ATT_PAD + dt * 8 + r];
                uint32_t b1 = VsU[(kk * 8 + cg + 4) * ATT_PAD + dt * 8 + r];
                mma_tf32(oc[dt], aP, b0, b1);
            }
        }
    }

    float inv0 = 1.0f / l0, inv1 = 1.0f / l1;
    float* O0 = O + (size_t)(qbase + qrow) * DM + cb;
    float* O1 = O + (size_t)(qbase + qrow + 8) * DM + cb;
#pragma unroll
    for (int dt = 0; dt < 8; dt++) {
        float2 v0 = { tf32f(oc[dt][0] * inv0), tf32f(oc[dt][1] * inv0) };
        float2 v1 = { tf32f(oc[dt][2] * inv1), tf32f(oc[dt][3] * inv1) };
        *reinterpret_cast<float2*>(O0 + dt * 8 + 2 * cg) = v0;
        *reinterpret_cast<float2*>(O1 + dt * 8 + 2 * cg) = v1;
    }
}

// ---------------------------------------------------------------------------
extern "C" void kernel_launch(void* const* d_in, const int* in_sizes, int n_in,
                              void* d_out, int out_size) {
    const float* X   = (const float*)d_in[0];
    const float* lnw = (const float*)d_in[1];
    const float* lnb = (const float*)d_in[2];
    const float* Wq  = (const float*)d_in[3];
    const float* bq  = (const float*)d_in[4];
    const float* Wk  = (const float*)d_in[5];
    const float* bk  = (const float*)d_in[6];
    const float* Wv  = (const float*)d_in[7];
    const float* bv  = (const float*)d_in[8];
    const float* Wo  = (const float*)d_in[9];
    const float* bo  = (const float*)d_in[10];
    float* out = (float*)d_out;
    (void)in_sizes; (void)n_in; (void)out_size;

    float *Xn, *Qb, *Kb, *Vb, *Mb, *Wt;
    cudaGetSymbolAddress((void**)&Xn, g_Xn);
    cudaGetSymbolAddress((void**)&Qb, g_Q);
    cudaGetSymbolAddress((void**)&Kb, g_K);
    cudaGetSymbolAddress((void**)&Vb, g_V);
    cudaGetSymbolAddress((void**)&Mb, g_M);
    cudaGetSymbolAddress((void**)&Wt, g_Wt);

    cudaFuncSetAttribute(gemm_mma, cudaFuncAttributeMaxDynamicSharedMemorySize,
                         GEMM_SMEM);
    cudaFuncSetAttribute(attn_mma, cudaFuncAttributeMaxDynamicSharedMemorySize,
                         ATTN_SMEM);

    ln_kernel<<<NTOK, 256>>>(X, lnw, lnb, Xn);

    dim3 ggrid(DM / 128, NTOK / 128);          // (8, 32)
    int rblk = (DM * DM) / (256 * 4);          // 1024 blocks

    round_tf32<<<rblk, 256>>>(Wq, Wt);
    gemm_mma<<<ggrid, 256, GEMM_SMEM>>>(Xn, Wt, bq, Qb);
    round_tf32<<<rblk, 256>>>(Wk, Wt);
    gemm_mma<<<ggrid, 256, GEMM_SMEM>>>(Xn, Wt, bk, Kb);
    round_tf32<<<rblk, 256>>>(Wv, Wt);
    gemm_mma<<<ggrid, 256, GEMM_SMEM>>>(Xn, Wt, bv, Vb);

    dim3 agrid(SEQ / 64, 2 * NH);              // (32, 32)
    attn_mma<<<agrid, 128, ATTN_SMEM>>>(Qb, Kb, Vb, Mb);

    round_tf32<<<rblk, 256>>>(Wo, Wt);
    gemm_mma<<<ggrid, 256, GEMM_SMEM>>>(Mb, Wt, bo, out);
}